// round 2
// baseline (speedup 1.0000x reference)
#include <cuda_runtime.h>
#include <cuda_bf16.h>
#include <cstdint>

// ---------------------------------------------------------------------------
// DCNv2 fused: offsets/mask conv -> modulated deformable conv (implicit GEMM)
// B=8, C1=C2=256, H=W=64, K=3, stride=1, pad=1
// ---------------------------------------------------------------------------

#define Bsz   8
#define C1    256
#define C2    256
#define Hd    64
#define Wd    64
#define HW    4096      // 64*64
#define KTOT  2304      // C1*9

// scratch (device globals: allocation-free rule)
__device__ float g_offset[Bsz * 18 * HW];   // clipped offsets, conv layout [B,18,H,W]
__device__ float g_mask  [Bsz * 9  * HW];   // sigmoid masks   [B,9,H,W]
__device__ float g_wt    [KTOT * C2];       // reg_w transposed: [k][c2]

// ---------------- f32x2 helpers (packed fp32 FMA: 2x FFMA throughput) ------
__device__ __forceinline__ void fma2(unsigned long long &d,
                                     unsigned long long a,
                                     unsigned long long b) {
    asm("fma.rn.f32x2 %0, %1, %2, %0;" : "+l"(d) : "l"(a), "l"(b));
}
__device__ __forceinline__ unsigned long long pack2(float v) {
    unsigned long long r;
    asm("mov.b64 %0, {%1, %2};" : "=l"(r) : "f"(v), "f"(v));
    return r;
}
__device__ __forceinline__ float2 unpack2(unsigned long long v) {
    float2 f;
    asm("mov.b64 {%0, %1}, %2;" : "=f"(f.x), "=f"(f.y) : "l"(v));
    return f;
}

// ---------------------------------------------------------------------------
// Kernel 0: transpose reg_w [C2][KTOT] -> g_wt [KTOT][C2]
// ---------------------------------------------------------------------------
__global__ void wt_transpose_kernel(const float* __restrict__ regw) {
    int idx = blockIdx.x * 1024 + threadIdx.x;   // 0 .. 589823
    if (idx < C2 * KTOT) {
        int c2 = idx / KTOT;
        int k  = idx - c2 * KTOT;
        g_wt[k * C2 + c2] = regw[idx];
    }
}

// ---------------------------------------------------------------------------
// Kernel 1: offset (clip +-16) + modulator (sigmoid) conv, 27 out channels.
// grid (16 tiles, B), block 256 = 16x16 positions, loop over 256 input chans.
// ---------------------------------------------------------------------------
__global__ void offmod_kernel(const float* __restrict__ x,
                              const float* __restrict__ offw,
                              const float* __restrict__ offb,
                              const float* __restrict__ modw,
                              const float* __restrict__ modb) {
    __shared__ float xs[18 * 18];
    __shared__ float wsh[27 * 9];

    int tid = threadIdx.x;
    int b   = blockIdx.y;
    int th  = blockIdx.x >> 2, tw = blockIdx.x & 3;
    int h0  = th << 4, w0 = tw << 4;
    int ty  = tid >> 4, tx = tid & 15;

    float acc[27];
#pragma unroll
    for (int i = 0; i < 27; ++i) acc[i] = 0.f;

    for (int c1 = 0; c1 < C1; ++c1) {
        const float* xp = x + ((b * C1 + c1) << 12);
        for (int idx = tid; idx < 324; idx += 256) {
            int ly = idx / 18, lx = idx - ly * 18;
            int gy = h0 - 1 + ly, gx = w0 - 1 + lx;
            float v = 0.f;
            if (gy >= 0 && gy < Hd && gx >= 0 && gx < Wd)
                v = xp[(gy << 6) + gx];
            xs[idx] = v;
        }
        if (tid < 243) {
            int oc = tid / 9, tap = tid - oc * 9;
            wsh[tid] = (oc < 18) ? offw[(oc * C1 + c1) * 9 + tap]
                                 : modw[((oc - 18) * C1 + c1) * 9 + tap];
        }
        __syncthreads();
#pragma unroll
        for (int tap = 0; tap < 9; ++tap) {
            int ky = tap / 3, kx = tap - ky * 3;
            float xv = xs[(ty + ky) * 18 + tx + kx];
#pragma unroll
            for (int oc = 0; oc < 27; ++oc)
                acc[oc] += xv * wsh[oc * 9 + tap];
        }
        __syncthreads();
    }

    int h = h0 + ty, w = w0 + tx;
    int pix = (h << 6) + w;
#pragma unroll
    for (int oc = 0; oc < 18; ++oc) {
        float v = acc[oc] + offb[oc];
        v = fminf(fmaxf(v, -16.f), 16.f);        // max_offset = 64/4
        g_offset[((b * 18 + oc) << 12) + pix] = v;
    }
#pragma unroll
    for (int oc = 0; oc < 9; ++oc) {
        float v = acc[18 + oc] + modb[oc];
        g_mask[((b * 9 + oc) << 12) + pix] = 1.f / (1.f + __expf(-v));
    }
}

// ---------------------------------------------------------------------------
// Kernel 2: fused deformable implicit GEMM.
// Tile: BM=128 (c2), BN=128 (2 rows x 64 cols of one image), BK=18 (2 c1 x 9).
// Bilinear params (mask+validity folded into 4 corner weights, 4 packed
// 16-bit gather indices) precomputed per block into shared.
// GEMM core: fma.rn.f32x2, accumulators paired along M.
// ---------------------------------------------------------------------------
__global__ __launch_bounds__(256, 2)
void dconv_kernel(const float* __restrict__ x, float* __restrict__ out) {
    __shared__ float  As[18 * 128];      //  9216 B  As[k][m]
    __shared__ float  Bs[18 * 128];      //  9216 B  Bs[k][n]
    __shared__ float4 Pw[9 * 128];       // 18432 B  corner weights per (tap,n)
    __shared__ uint2  Pi[9 * 128];       //  9216 B  packed corner indices

    int tid  = threadIdx.x;
    int b    = blockIdx.x >> 5;
    int h0   = (blockIdx.x & 31) << 1;   // two consecutive rows
    int c2_0 = blockIdx.y << 7;

    // ---- per-block bilinear parameters: 9 taps x 128 positions ----
    for (int idx = tid; idx < 1152; idx += 256) {
        int tap = idx >> 7, n = idx & 127;
        int h = h0 + (n >> 6), w = n & 63;
        int pix   = (h << 6) + w;
        int obase = ((b * 18 + tap * 2) << 12) + pix;
        float dy = g_offset[obase];
        float dx = g_offset[obase + 4096];
        float m  = g_mask[((b * 9 + tap) << 12) + pix];
        float py = dy + (float)(tap / 3 + h - 1);
        float px = dx + (float)(tap % 3 + w - 1);
        float y0f = floorf(py), x0f = floorf(px);
        float ly = py - y0f,   lx = px - x0f;
        int y0 = (int)y0f, x0 = (int)x0f;
        int y1 = y0 + 1,   x1 = x0 + 1;
        float vy0 = (y0 >= 0 && y0 < Hd) ? m : 0.f;
        float vy1 = (y1 >= 0 && y1 < Hd) ? m : 0.f;
        float vx0 = (x0 >= 0 && x0 < Wd) ? 1.f : 0.f;
        float vx1 = (x1 >= 0 && x1 < Wd) ? 1.f : 0.f;
        float4 wv;
        wv.x = (1.f - ly) * (1.f - lx) * vy0 * vx0;
        wv.y = (1.f - ly) * lx         * vy0 * vx1;
        wv.z = ly         * (1.f - lx) * vy1 * vx0;
        wv.w = ly         * lx         * vy1 * vx1;
        int cy0 = min(max(y0, 0), Hd - 1) << 6;
        int cy1 = min(max(y1, 0), Hd - 1) << 6;
        int cx0 = min(max(x0, 0), Wd - 1);
        int cx1 = min(max(x1, 0), Wd - 1);
        uint2 pk;
        pk.x = (unsigned)(cy0 + cx0) | ((unsigned)(cy0 + cx1) << 16);
        pk.y = (unsigned)(cy1 + cx0) | ((unsigned)(cy1 + cx1) << 16);
        Pw[idx] = wv;
        Pi[idx] = pk;
    }
    __syncthreads();

    unsigned long long acc2[4][8];
#pragma unroll
    for (int i = 0; i < 4; ++i)
#pragma unroll
        for (int j = 0; j < 8; ++j) acc2[i][j] = 0ull;

    int ty   = tid >> 4, tx = tid & 15;
    int nloc = tid & 127;
    int c1h  = tid >> 7;                 // 0 or 1: which local c1 this thread builds

    for (int chunk = 0; chunk < 128; ++chunk) {
        int kbase = chunk * 18;          // = (chunk*2)*9
        // A tile: As[kk][m] = g_wt[kbase+kk][c2_0+m]  (coalesced)
#pragma unroll
        for (int i = 0; i < 9; ++i) {
            int idx = tid + (i << 8);
            int kk = idx >> 7, mm = idx & 127;
            As[kk * 128 + mm] = g_wt[(kbase + kk) * C2 + c2_0 + mm];
        }
        // B tile: gather bilinear samples for 2 input channels x 9 taps
        {
            const float* xp = x + ((b * C1 + (chunk << 1) + c1h) << 12);
#pragma unroll
            for (int tap = 0; tap < 9; ++tap) {
                float4 wv = Pw[tap * 128 + nloc];
                uint2  pk = Pi[tap * 128 + nloc];
                float v = wv.x * xp[pk.x & 0xFFFFu]
                        + wv.y * xp[pk.x >> 16]
                        + wv.z * xp[pk.y & 0xFFFFu]
                        + wv.w * xp[pk.y >> 16];
                Bs[(c1h * 9 + tap) * 128 + nloc] = v;
            }
        }
        __syncthreads();

#pragma unroll
        for (int k = 0; k < 18; ++k) {
            ulonglong2 A0 = *(const ulonglong2*)&As[k * 128 + (ty << 2)];
            ulonglong2 A1 = *(const ulonglong2*)&As[k * 128 + 64 + (ty << 2)];
            float4 b0 = *(const float4*)&Bs[k * 128 + (tx << 2)];
            float4 b1 = *(const float4*)&Bs[k * 128 + 64 + (tx << 2)];
            unsigned long long bd[8];
            bd[0] = pack2(b0.x); bd[1] = pack2(b0.y);
            bd[2] = pack2(b0.z); bd[3] = pack2(b0.w);
            bd[4] = pack2(b1.x); bd[5] = pack2(b1.y);
            bd[6] = pack2(b1.z); bd[7] = pack2(b1.w);
#pragma unroll
            for (int j = 0; j < 8; ++j) {
                fma2(acc2[0][j], A0.x, bd[j]);
                fma2(acc2[1][j], A0.y, bd[j]);
                fma2(acc2[2][j], A1.x, bd[j]);
                fma2(acc2[3][j], A1.y, bd[j]);
            }
        }
        __syncthreads();
    }

    // ---- epilogue: unpack pairs, vectorized stores (positions contiguous) ----
#pragma unroll
    for (int mm = 0; mm < 4; ++mm) {
        int m_even = (mm < 2) ? ((ty << 2) + mm * 2)
                              : (64 + (ty << 2) + (mm - 2) * 2);
        float4 lo0, lo1, hi0, hi1;
        float2 u;
        u = unpack2(acc2[mm][0]); lo0.x = u.x; hi0.x = u.y;
        u = unpack2(acc2[mm][1]); lo0.y = u.x; hi0.y = u.y;
        u = unpack2(acc2[mm][2]); lo0.z = u.x; hi0.z = u.y;
        u = unpack2(acc2[mm][3]); lo0.w = u.x; hi0.w = u.y;
        u = unpack2(acc2[mm][4]); lo1.x = u.x; hi1.x = u.y;
        u = unpack2(acc2[mm][5]); lo1.y = u.x; hi1.y = u.y;
        u = unpack2(acc2[mm][6]); lo1.z = u.x; hi1.z = u.y;
        u = unpack2(acc2[mm][7]); lo1.w = u.x; hi1.w = u.y;
        float* op0 = out + ((b * C2 + c2_0 + m_even) << 12) + (h0 << 6);
        float* op1 = op0 + 4096;
        *(float4*)&op0[tx << 2]      = lo0;
        *(float4*)&op0[64 + (tx << 2)] = lo1;
        *(float4*)&op1[tx << 2]      = hi0;
        *(float4*)&op1[64 + (tx << 2)] = hi1;
    }
}

// ---------------------------------------------------------------------------
extern "C" void kernel_launch(void* const* d_in, const int* in_sizes, int n_in,
                              void* d_out, int out_size) {
    (void)in_sizes; (void)n_in; (void)out_size;
    const float* x    = (const float*)d_in[0];
    const float* offw = (const float*)d_in[1];
    const float* offb = (const float*)d_in[2];
    const float* modw = (const float*)d_in[3];
    const float* modb = (const float*)d_in[4];
    const float* regw = (const float*)d_in[5];
    float* out = (float*)d_out;

    wt_transpose_kernel<<<576, 1024>>>(regw);
    offmod_kernel<<<dim3(16, 8), 256>>>(x, offw, offb, modw, modb);
    dconv_kernel<<<dim3(256, 2), 256>>>(x, out);
}

// round 4
// speedup vs baseline: 2.4770x; 2.4770x over previous
#include <cuda_runtime.h>
#include <cuda_bf16.h>
#include <cstdint>

// ---------------------------------------------------------------------------
// DCNv2: offsets/mask conv -> modulated deformable conv via mma.sync bf16
// (3-pass hi/lo split for fp32-grade accuracy on the tensor pipe).
// B=8, C1=C2=256, H=W=64, K=3, stride=1, pad=1
// GEMM view: M=C2=256, N=B*H*W=32768, K=2304 with k = tap*256 + c1
// ---------------------------------------------------------------------------

#define Bsz   8
#define C1    256
#define C2    256
#define Hd    64
#define Wd    64
#define HW    4096
#define KTOT  2304

__device__ float          g_offset[Bsz * 18 * HW];
__device__ float          g_mask  [Bsz * 9  * HW];
__device__ __nv_bfloat16  g_wh    [C2 * KTOT];   // [c2][tap*256+c1] bf16 hi
__device__ __nv_bfloat16  g_wl    [C2 * KTOT];   // residual lo (bf16)

// ---------------- helpers ---------------------------------------------------
__device__ __forceinline__ uint32_t smem_u32(const void* p) {
    uint32_t a;
    asm("{ .reg .u64 t; cvta.to.shared.u64 t, %1; cvt.u32.u64 %0, t; }"
        : "=r"(a) : "l"(p));
    return a;
}
__device__ __forceinline__ void ldm_x4(uint32_t* r, uint32_t a) {
    asm volatile("ldmatrix.sync.aligned.m8n8.x4.shared.b16 {%0,%1,%2,%3}, [%4];"
                 : "=r"(r[0]), "=r"(r[1]), "=r"(r[2]), "=r"(r[3]) : "r"(a));
}
__device__ __forceinline__ void ldm_x2(uint32_t* r, uint32_t a) {
    asm volatile("ldmatrix.sync.aligned.m8n8.x2.shared.b16 {%0,%1}, [%2];"
                 : "=r"(r[0]), "=r"(r[1]) : "r"(a));
}
__device__ __forceinline__ void mma_bf16(float* d, const uint32_t* a,
                                         const uint32_t* b) {
    asm volatile(
        "mma.sync.aligned.m16n8k16.row.col.f32.bf16.bf16.f32 "
        "{%0,%1,%2,%3}, {%4,%5,%6,%7}, {%8,%9}, {%0,%1,%2,%3};"
        : "+f"(d[0]), "+f"(d[1]), "+f"(d[2]), "+f"(d[3])
        : "r"(a[0]), "r"(a[1]), "r"(a[2]), "r"(a[3]), "r"(b[0]), "r"(b[1]));
}
// pack two fp32 -> bf16x2 (v1 high, v0 low)
__device__ __forceinline__ uint32_t bf16x2(float v1, float v0) {
    uint32_t u;
    asm("cvt.rn.bf16x2.f32 %0, %1, %2;" : "=r"(u) : "f"(v1), "f"(v0));
    return u;
}

// ---------------------------------------------------------------------------
// Kernel 0: split reg_w into bf16 hi/lo, reorder k -> tap*256 + c1
// ---------------------------------------------------------------------------
__global__ void wt_split_kernel(const float* __restrict__ regw) {
    int idx = blockIdx.x * 1024 + threadIdx.x;
    if (idx < C2 * KTOT) {
        int c2 = idx / KTOT;
        int r  = idx - c2 * KTOT;     // c1*9 + tap
        int c1 = r / 9, tap = r - c1 * 9;
        float v = regw[idx];
        __nv_bfloat16 hb = __float2bfloat16_rn(v);
        float lo = v - __bfloat162float(hb);
        int ko = c2 * KTOT + tap * 256 + c1;
        g_wh[ko] = hb;
        g_wl[ko] = __float2bfloat16_rn(lo);
    }
}

// ---------------------------------------------------------------------------
// Kernel 1: offset (clip +-16) + modulator (sigmoid) conv, 27 out channels.
// ---------------------------------------------------------------------------
__global__ void offmod_kernel(const float* __restrict__ x,
                              const float* __restrict__ offw,
                              const float* __restrict__ offb,
                              const float* __restrict__ modw,
                              const float* __restrict__ modb) {
    __shared__ float xs[18 * 18];
    __shared__ float wsh[27 * 9];

    int tid = threadIdx.x;
    int b   = blockIdx.y;
    int th  = blockIdx.x >> 2, tw = blockIdx.x & 3;
    int h0  = th << 4, w0 = tw << 4;
    int ty  = tid >> 4, tx = tid & 15;

    float acc[27];
#pragma unroll
    for (int i = 0; i < 27; ++i) acc[i] = 0.f;

    for (int c1 = 0; c1 < C1; ++c1) {
        const float* xp = x + ((b * C1 + c1) << 12);
        for (int idx = tid; idx < 324; idx += 256) {
            int ly = idx / 18, lx = idx - ly * 18;
            int gy = h0 - 1 + ly, gx = w0 - 1 + lx;
            float v = 0.f;
            if (gy >= 0 && gy < Hd && gx >= 0 && gx < Wd)
                v = xp[(gy << 6) + gx];
            xs[idx] = v;
        }
        if (tid < 243) {
            int oc = tid / 9, tap = tid - oc * 9;
            wsh[tid] = (oc < 18) ? offw[(oc * C1 + c1) * 9 + tap]
                                 : modw[((oc - 18) * C1 + c1) * 9 + tap];
        }
        __syncthreads();
#pragma unroll
        for (int tap = 0; tap < 9; ++tap) {
            int ky = tap / 3, kx = tap - ky * 3;
            float xv = xs[(ty + ky) * 18 + tx + kx];
#pragma unroll
            for (int oc = 0; oc < 27; ++oc)
                acc[oc] += xv * wsh[oc * 9 + tap];
        }
        __syncthreads();
    }

    int h = h0 + ty, w = w0 + tx;
    int pix = (h << 6) + w;
#pragma unroll
    for (int oc = 0; oc < 18; ++oc) {
        float v = acc[oc] + offb[oc];
        v = fminf(fmaxf(v, -16.f), 16.f);
        g_offset[((b * 18 + oc) << 12) + pix] = v;
    }
#pragma unroll
    for (int oc = 0; oc < 9; ++oc) {
        float v = acc[18 + oc] + modb[oc];
        g_mask[((b * 9 + oc) << 12) + pix] = 1.f / (1.f + __expf(-v));
    }
}

// ---------------------------------------------------------------------------
// Kernel 2: deformable implicit GEMM on mma.sync bf16 (3-pass split).
// BM=128 (c2), BN=128 (2 rows of one image), BK=32 (one tap, 32 c1).
// smem tiles padded to 80B rows (conflict-free ldmatrix). 2 CTAs/SM.
// ---------------------------------------------------------------------------
#define ASTR 80
#define OFF_AH 0
#define OFF_AL 10240
#define OFF_BH 20480
#define OFF_BL 30720
#define OFF_PW 40960            // float4[1152] = 18432
#define OFF_PI 59392            // uint2 [1152] =  9216
#define SMEM_DYN 68608

__global__ __launch_bounds__(256, 2)
void dconv_mma(const float* __restrict__ x, float* __restrict__ out) {
    extern __shared__ char smem[];
    uint32_t sb  = smem_u32(smem);
    uint32_t sAh = sb + OFF_AH, sAl = sb + OFF_AL;
    uint32_t sBh = sb + OFF_BH, sBl = sb + OFF_BL;
    float4* Pw = (float4*)(smem + OFF_PW);
    uint2*  Pi = (uint2*)(smem + OFF_PI);

    int tid  = threadIdx.x;
    int lane = tid & 31, wid = tid >> 5;
    int mw   = wid >> 2, nw = wid & 3;        // warp tile: 64m x 32n

    int nt   = blockIdx.x;                    // 0..255
    int b    = nt >> 5;
    int pix0 = (nt & 31) << 7;                // 128 consecutive pixels = 2 rows
    int h0   = pix0 >> 6;
    int c2_0 = blockIdx.y << 7;

    // ---- bilinear params: 9 taps x 128 positions (once per CTA) ----
    for (int idx = tid; idx < 1152; idx += 256) {
        int tap = idx >> 7, n = idx & 127;
        int h = h0 + (n >> 6), w = n & 63;
        int pix   = (h << 6) + w;
        int obase = ((b * 18 + tap * 2) << 12) + pix;
        float dy = g_offset[obase];
        float dx = g_offset[obase + 4096];
        float m  = g_mask[((b * 9 + tap) << 12) + pix];
        float py = dy + (float)(tap / 3 + h - 1);
        float px = dx + (float)(tap % 3 + w - 1);
        float y0f = floorf(py), x0f = floorf(px);
        float ly = py - y0f, lx = px - x0f;
        int y0 = (int)y0f, x0 = (int)x0f;
        int y1 = y0 + 1,   x1 = x0 + 1;
        float vy0 = (y0 >= 0 && y0 < Hd) ? m : 0.f;
        float vy1 = (y1 >= 0 && y1 < Hd) ? m : 0.f;
        float vx0 = (x0 >= 0 && x0 < Wd) ? 1.f : 0.f;
        float vx1 = (x1 >= 0 && x1 < Wd) ? 1.f : 0.f;
        float4 wv;
        wv.x = (1.f - ly) * (1.f - lx) * vy0 * vx0;
        wv.y = (1.f - ly) * lx         * vy0 * vx1;
        wv.z = ly         * (1.f - lx) * vy1 * vx0;
        wv.w = ly         * lx         * vy1 * vx1;
        int cy0 = min(max(y0, 0), Hd - 1) << 6;
        int cy1 = min(max(y1, 0), Hd - 1) << 6;
        int cx0 = min(max(x0, 0), Wd - 1);
        int cx1 = min(max(x1, 0), Wd - 1);
        uint2 pk;
        pk.x = (unsigned)(cy0 + cx0) | ((unsigned)(cy0 + cx1) << 16);
        pk.y = (unsigned)(cy1 + cx0) | ((unsigned)(cy1 + cx1) << 16);
        Pw[idx] = wv;
        Pi[idx] = pk;
    }

    float acc[4][4][4];
#pragma unroll
    for (int i = 0; i < 4; ++i)
#pragma unroll
        for (int j = 0; j < 4; ++j)
#pragma unroll
            for (int q = 0; q < 4; ++q) acc[i][j][q] = 0.f;

    int n_me = tid & 127;
    int kh   = tid >> 7;                      // 0/1: which 16-channel half

    for (int c = 0; c < 72; ++c) {
        int tap = c >> 3, c1b = (c & 7) << 5;
        int kbase = tap * 256 + c1b;
        __syncthreads();                       // smem safe to overwrite

        // A tiles hi/lo: As[m][k], 64B data rows padded to 80B
        {
            const __nv_bfloat16* whp = g_wh + (size_t)c2_0 * KTOT + kbase;
            const __nv_bfloat16* wlp = g_wl + (size_t)c2_0 * KTOT + kbase;
#pragma unroll
            for (int i = 0; i < 2; ++i) {
                int idx = tid + (i << 8);      // 0..511
                int m = idx >> 2, g = idx & 3;
                *(uint4*)(smem + OFF_AH + m * ASTR + g * 16) =
                    *(const uint4*)(whp + (size_t)m * KTOT + g * 8);
                *(uint4*)(smem + OFF_AL + m * ASTR + g * 16) =
                    *(const uint4*)(wlp + (size_t)m * KTOT + g * 8);
            }
        }
        // B tiles: fp32 bilinear gather -> bf16 hi/lo split
        {
            float4 wv = Pw[tap * 128 + n_me];
            uint2  pk = Pi[tap * 128 + n_me];
            uint32_t i00 = pk.x & 0xFFFFu, i01 = pk.x >> 16;
            uint32_t i10 = pk.y & 0xFFFFu, i11 = pk.y >> 16;
            const float* xb = x + ((size_t)(b * C1 + c1b + kh * 16) << 12);
            uint32_t bhreg[8], blreg[8];
#pragma unroll
            for (int q = 0; q < 8; ++q) {
                const float* x0p = xb + ((q * 2)     << 12);
                const float* x1p = xb + ((q * 2 + 1) << 12);
                float v0 = wv.x * x0p[i00] + wv.y * x0p[i01]
                         + wv.z * x0p[i10] + wv.w * x0p[i11];
                float v1 = wv.x * x1p[i00] + wv.y * x1p[i01]
                         + wv.z * x1p[i10] + wv.w * x1p[i11];
                uint32_t uh = bf16x2(v1, v0);
                float h0f = __uint_as_float(uh << 16);
                float h1f = __uint_as_float(uh & 0xFFFF0000u);
                bhreg[q] = uh;
                blreg[q] = bf16x2(v1 - h1f, v0 - h0f);
            }
            uint32_t off = n_me * ASTR + kh * 32;
            *(uint4*)(smem + OFF_BH + off)      = make_uint4(bhreg[0], bhreg[1], bhreg[2], bhreg[3]);
            *(uint4*)(smem + OFF_BH + off + 16) = make_uint4(bhreg[4], bhreg[5], bhreg[6], bhreg[7]);
            *(uint4*)(smem + OFF_BL + off)      = make_uint4(blreg[0], blreg[1], blreg[2], blreg[3]);
            *(uint4*)(smem + OFF_BL + off + 16) = make_uint4(blreg[4], blreg[5], blreg[6], blreg[7]);
        }
        __syncthreads();

        // ---- mma: 2 k-steps of 16 ----
        int lr = lane & 15, ls = lane >> 4;          // A ldmatrix row / k-half
        int br = lane & 7,  bs = (lane >> 3) & 1;    // B ldmatrix row / k-half
#pragma unroll
        for (int ks = 0; ks < 2; ++ks) {
            uint32_t bh[4][2], bl[4][2];
#pragma unroll
            for (int fn = 0; fn < 4; ++fn) {
                uint32_t ba = sBh + (nw * 32 + fn * 8 + br) * ASTR + ks * 32 + bs * 16;
                ldm_x2(bh[fn], ba);
                ldm_x2(bl[fn], ba + (OFF_BL - OFF_BH));
            }
#pragma unroll
            for (int fm = 0; fm < 4; ++fm) {
                uint32_t ah[4], al[4];
                uint32_t aa = sAh + (mw * 64 + fm * 16 + lr) * ASTR + ks * 32 + ls * 16;
                ldm_x4(ah, aa);
                ldm_x4(al, aa + (OFF_AL - OFF_AH));
#pragma unroll
                for (int fn = 0; fn < 4; ++fn) {
                    mma_bf16(acc[fm][fn], ah, bh[fn]);
                    mma_bf16(acc[fm][fn], ah, bl[fn]);
                    mma_bf16(acc[fm][fn], al, bh[fn]);
                }
            }
        }
    }

    // ---- epilogue: direct float2 stores ----
#pragma unroll
    for (int fm = 0; fm < 4; ++fm) {
#pragma unroll
        for (int fn = 0; fn < 4; ++fn) {
            int r0   = c2_0 + mw * 64 + fm * 16 + (lane >> 2);
            int ncol = pix0 + nw * 32 + fn * 8 + ((lane & 3) << 1);
            float* p0 = out + ((size_t)(b * C2 + r0) << 12) + ncol;
            float2 v0 = make_float2(acc[fm][fn][0], acc[fm][fn][1]);
            float2 v1 = make_float2(acc[fm][fn][2], acc[fm][fn][3]);
            *(float2*)p0 = v0;
            *(float2*)(p0 + (8u << 12)) = v1;   // row r0+8
        }
    }
}

// ---------------------------------------------------------------------------
extern "C" void kernel_launch(void* const* d_in, const int* in_sizes, int n_in,
                              void* d_out, int out_size) {
    (void)in_sizes; (void)n_in; (void)out_size;
    const float* x    = (const float*)d_in[0];
    const float* offw = (const float*)d_in[1];
    const float* offb = (const float*)d_in[2];
    const float* modw = (const float*)d_in[3];
    const float* modb = (const float*)d_in[4];
    const float* regw = (const float*)d_in[5];
    float* out = (float*)d_out;

    cudaFuncSetAttribute(dconv_mma, cudaFuncAttributeMaxDynamicSharedMemorySize,
                         SMEM_DYN);
    wt_split_kernel<<<576, 1024>>>(regw);
    offmod_kernel<<<dim3(16, 8), 256>>>(x, offw, offb, modw, modb);
    dconv_mma<<<dim3(256, 2), 256, SMEM_DYN>>>(x, out);
}

// round 5
// speedup vs baseline: 3.4636x; 1.3983x over previous
#include <cuda_runtime.h>
#include <cuda_bf16.h>
#include <cstdint>

// ---------------------------------------------------------------------------
// DCNv2 via mma.sync bf16 3-pass (hi/lo split), fully tensor-core:
//  K0 xt_kernel   : x NCHW -> HWC fp32 + bf16 hi/lo copies
//  K1 wt_split    : reg_w -> bf16 hi/lo, k = tap*256 + c1
//  K2 w27_split   : offset/mod weights -> bf16 hi/lo [32][2304]
//  K3 offmod_mma  : 27-channel conv on tensor cores -> g_offset/g_mask
//  K4 dconv_mma   : deformable implicit GEMM, double-buffered pipeline
// ---------------------------------------------------------------------------

#define Bsz   8
#define C1    256
#define C2    256
#define Hd    64
#define Wd    64
#define HW    4096
#define KTOT  2304

__device__ __align__(16) float         g_xt[Bsz * HW * C1];   // [b][pix][c]
__device__ __align__(16) __nv_bfloat16 g_xh[Bsz * HW * C1];
__device__ __align__(16) __nv_bfloat16 g_xl[Bsz * HW * C1];
__device__ __align__(16) __nv_bfloat16 g_wh[C2 * KTOT];       // [c2][tap*256+c1]
__device__ __align__(16) __nv_bfloat16 g_wl[C2 * KTOT];
__device__ __align__(16) __nv_bfloat16 g_w27h[32 * KTOT];     // [m][tap*256+c1]
__device__ __align__(16) __nv_bfloat16 g_w27l[32 * KTOT];
__device__ float g_offset[Bsz * 18 * HW];
__device__ float g_mask  [Bsz * 9  * HW];

// ---------------- helpers ---------------------------------------------------
__device__ __forceinline__ uint32_t smem_u32(const void* p) {
    uint32_t a;
    asm("{ .reg .u64 t; cvta.to.shared.u64 t, %1; cvt.u32.u64 %0, t; }"
        : "=r"(a) : "l"(p));
    return a;
}
__device__ __forceinline__ void ldm_x4(uint32_t* r, uint32_t a) {
    asm volatile("ldmatrix.sync.aligned.m8n8.x4.shared.b16 {%0,%1,%2,%3}, [%4];"
                 : "=r"(r[0]), "=r"(r[1]), "=r"(r[2]), "=r"(r[3]) : "r"(a));
}
__device__ __forceinline__ void ldm_x2(uint32_t* r, uint32_t a) {
    asm volatile("ldmatrix.sync.aligned.m8n8.x2.shared.b16 {%0,%1}, [%2];"
                 : "=r"(r[0]), "=r"(r[1]) : "r"(a));
}
__device__ __forceinline__ void mma_bf16(float* d, const uint32_t* a,
                                         const uint32_t* b) {
    asm volatile(
        "mma.sync.aligned.m16n8k16.row.col.f32.bf16.bf16.f32 "
        "{%0,%1,%2,%3}, {%4,%5,%6,%7}, {%8,%9}, {%0,%1,%2,%3};"
        : "+f"(d[0]), "+f"(d[1]), "+f"(d[2]), "+f"(d[3])
        : "r"(a[0]), "r"(a[1]), "r"(a[2]), "r"(a[3]), "r"(b[0]), "r"(b[1]));
}

// ---------------------------------------------------------------------------
// K0: transpose x [B][C][HW] -> [B][HW][C] fp32 + bf16 hi/lo
// ---------------------------------------------------------------------------
__global__ void xt_kernel(const float* __restrict__ x) {
    __shared__ float xs[32 * 129];
    int tid = threadIdx.x;
    int pb = blockIdx.x, cb = blockIdx.y, b = blockIdx.z;
    int pix0 = pb << 7, c0 = cb << 5;
#pragma unroll
    for (int j = 0; j < 16; ++j) {
        int idx = tid + (j << 8);
        int ci = idx >> 7, pi = idx & 127;
        xs[ci * 129 + pi] = x[((size_t)(b * C1 + c0 + ci) << 12) + pix0 + pi];
    }
    __syncthreads();
    int lane = tid & 31, wid = tid >> 5;
#pragma unroll
    for (int j = 0; j < 16; ++j) {
        int pix = wid * 16 + j;
        float v = xs[lane * 129 + pix];
        size_t o = ((size_t)((b << 12) + pix0 + pix) << 8) + c0 + lane;
        __nv_bfloat16 hb = __float2bfloat16_rn(v);
        g_xt[o] = v;
        g_xh[o] = hb;
        g_xl[o] = __float2bfloat16_rn(v - __bfloat162float(hb));
    }
}

// ---------------------------------------------------------------------------
// K1: split reg_w into bf16 hi/lo, reorder k -> tap*256 + c1
// ---------------------------------------------------------------------------
__global__ void wt_split_kernel(const float* __restrict__ regw) {
    int idx = blockIdx.x * 1024 + threadIdx.x;
    if (idx < C2 * KTOT) {
        int c2 = idx / KTOT;
        int r  = idx - c2 * KTOT;     // c1*9 + tap
        int c1 = r / 9, tap = r - c1 * 9;
        float v = regw[idx];
        __nv_bfloat16 hb = __float2bfloat16_rn(v);
        int ko = c2 * KTOT + tap * 256 + c1;
        g_wh[ko] = hb;
        g_wl[ko] = __float2bfloat16_rn(v - __bfloat162float(hb));
    }
}

// ---------------------------------------------------------------------------
// K2: offset/mod conv weights -> bf16 hi/lo [32][tap*256+c1] (rows 27..31 = 0)
// ---------------------------------------------------------------------------
__global__ void w27_split_kernel(const float* __restrict__ offw,
                                 const float* __restrict__ modw) {
    int idx = blockIdx.x * 256 + threadIdx.x;
    if (idx >= 32 * KTOT) return;
    int m = idx / KTOT, k = idx - m * KTOT;
    int tap = k >> 8, c1 = k & 255;
    float v = 0.f;
    if (m < 18)      v = offw[(m * C1 + c1) * 9 + tap];
    else if (m < 27) v = modw[((m - 18) * C1 + c1) * 9 + tap];
    __nv_bfloat16 hb = __float2bfloat16_rn(v);
    g_w27h[idx] = hb;
    g_w27l[idx] = __float2bfloat16_rn(v - __bfloat162float(hb));
}

// ---------------------------------------------------------------------------
// K3: offset+mask conv as tensor GEMM: M=32(27), N=128 px/CTA, K=2304.
// B = shifted (im2col) loads of g_xh/g_xl (HWC, coalesced). 3-pass bf16.
// ---------------------------------------------------------------------------
#define ASTR 80
__global__ __launch_bounds__(256)
void offmod_mma(const float* __restrict__ offb, const float* __restrict__ modb) {
    __shared__ __align__(16) char sm[25600];
    // AH 0 (2560), AL 2560, BH 5120 (10240), BL 15360
    uint32_t sb = smem_u32(sm);
    int tid = threadIdx.x, lane = tid & 31, wid = tid >> 5;
    int b = blockIdx.x >> 5;
    int h0 = (blockIdx.x & 31) << 1;
    int pix0 = h0 << 6;

    float acc[2][2][4];
#pragma unroll
    for (int i = 0; i < 2; ++i)
#pragma unroll
        for (int j = 0; j < 2; ++j)
#pragma unroll
            for (int q = 0; q < 4; ++q) acc[i][j][q] = 0.f;

    for (int c = 0; c < 72; ++c) {
        int tap = c >> 3, c1b = (c & 7) << 5;
        int kbase = tap * 256 + c1b;
        __syncthreads();
        {   // A tile: 32 x 32
            int m = tid >> 3, g = tid & 7;
            *(uint2*)(sm + m * ASTR + g * 8) =
                *(const uint2*)(g_w27h + (size_t)m * KTOT + kbase + g * 4);
            *(uint2*)(sm + 2560 + m * ASTR + g * 8) =
                *(const uint2*)(g_w27l + (size_t)m * KTOT + kbase + g * 4);
        }
        {   // B tile: im2col shifted loads, warp-per-pixel, lanes = channels
            int dy = tap / 3 - 1, dx = tap % 3 - 1;
#pragma unroll
            for (int i = 0; i < 16; ++i) {
                int n = wid * 16 + i;
                int h = h0 + (n >> 6), w = n & 63;
                int sy = h + dy, sx = w + dx;
                __nv_bfloat16 vh = __float2bfloat16_rn(0.f), vl = vh;
                if ((unsigned)sy < 64u && (unsigned)sx < 64u) {
                    size_t src = ((size_t)((b << 12) + (sy << 6) + sx) << 8)
                               + c1b + lane;
                    vh = g_xh[src];
                    vl = g_xl[src];
                }
                *(__nv_bfloat16*)(sm + 5120  + n * ASTR + lane * 2) = vh;
                *(__nv_bfloat16*)(sm + 15360 + n * ASTR + lane * 2) = vl;
            }
        }
        __syncthreads();

        int lr = lane & 15, ls = lane >> 4;
        int br = lane & 7,  bs = (lane >> 3) & 1;
#pragma unroll
        for (int ks = 0; ks < 2; ++ks) {
            uint32_t bh[2][2], bl[2][2];
#pragma unroll
            for (int fn = 0; fn < 2; ++fn) {
                uint32_t ba = sb + 5120 + (wid * 16 + fn * 8 + br) * ASTR
                            + ks * 32 + bs * 16;
                ldm_x2(bh[fn], ba);
                ldm_x2(bl[fn], ba + 10240);
            }
#pragma unroll
            for (int fm = 0; fm < 2; ++fm) {
                uint32_t ah[4], al[4];
                uint32_t aa = sb + (fm * 16 + lr) * ASTR + ks * 32 + ls * 16;
                ldm_x4(ah, aa);
                ldm_x4(al, aa + 2560);
#pragma unroll
                for (int fn = 0; fn < 2; ++fn) {
                    mma_bf16(acc[fm][fn], ah, bh[fn]);
                    mma_bf16(acc[fm][fn], ah, bl[fn]);
                    mma_bf16(acc[fm][fn], al, bh[fn]);
                }
            }
        }
    }

    // epilogue: rows 0-17 -> clipped offsets; 18-26 -> sigmoid masks
#pragma unroll
    for (int fm = 0; fm < 2; ++fm) {
#pragma unroll
        for (int fn = 0; fn < 2; ++fn) {
            int co  = wid * 16 + fn * 8 + ((lane & 3) << 1);
            int pix = pix0 + co;
#pragma unroll
            for (int half = 0; half < 2; ++half) {
                int r = fm * 16 + (lane >> 2) + half * 8;
                float v0 = acc[fm][fn][half * 2 + 0];
                float v1 = acc[fm][fn][half * 2 + 1];
                if (r < 18) {
                    float bb = __ldg(&offb[r]);
                    float a0 = fminf(fmaxf(v0 + bb, -16.f), 16.f);
                    float a1 = fminf(fmaxf(v1 + bb, -16.f), 16.f);
                    *(float2*)&g_offset[((size_t)(b * 18 + r) << 12) + pix] =
                        make_float2(a0, a1);
                } else if (r < 27) {
                    float bb = __ldg(&modb[r - 18]);
                    float a0 = 1.f / (1.f + __expf(-(v0 + bb)));
                    float a1 = 1.f / (1.f + __expf(-(v1 + bb)));
                    *(float2*)&g_mask[((size_t)(b * 9 + r - 18) << 12) + pix] =
                        make_float2(a0, a1);
                }
            }
        }
    }
}

// ---------------------------------------------------------------------------
// K4: deformable implicit GEMM, bf16 3-pass, double-buffered pipeline.
// BM=128, BN=128 (2 rows), BK=32 (one tap, 32 ch). Gather from HWC fp32 x.
// ---------------------------------------------------------------------------
#define ST_AH 0
#define ST_AL 10240
#define ST_BH 20480
#define ST_BL 30720
#define STAGE 40960
#define OFF_PW 81920          // float4[1152] = 18432
#define OFF_PI 100352         // uint2 [1152] =  9216
#define SMEM_DYN 109568

__global__ __launch_bounds__(256, 2)
void dconv_mma(float* __restrict__ out) {
    extern __shared__ char smem[];
    uint32_t sb = smem_u32(smem);
    float4* Pw = (float4*)(smem + OFF_PW);
    uint2*  Pi = (uint2*)(smem + OFF_PI);

    int tid = threadIdx.x, lane = tid & 31, wid = tid >> 5;
    int mw = wid >> 2, nw = wid & 3;

    int nt   = blockIdx.x;
    int b    = nt >> 5;
    int pix0 = (nt & 31) << 7;
    int h0   = pix0 >> 6;
    int c2_0 = blockIdx.y << 7;

    // ---- bilinear params: 9 taps x 128 positions ----
    for (int idx = tid; idx < 1152; idx += 256) {
        int tap = idx >> 7, n = idx & 127;
        int h = h0 + (n >> 6), w = n & 63;
        int pix   = (h << 6) + w;
        int obase = ((b * 18 + tap * 2) << 12) + pix;
        float dy = g_offset[obase];
        float dx = g_offset[obase + 4096];
        float m  = g_mask[((b * 9 + tap) << 12) + pix];
        float py = dy + (float)(tap / 3 + h - 1);
        float px = dx + (float)(tap % 3 + w - 1);
        float y0f = floorf(py), x0f = floorf(px);
        float ly = py - y0f, lx = px - x0f;
        int y0 = (int)y0f, x0 = (int)x0f;
        int y1 = y0 + 1,   x1 = x0 + 1;
        float vy0 = (y0 >= 0 && y0 < Hd) ? m : 0.f;
        float vy1 = (y1 >= 0 && y1 < Hd) ? m : 0.f;
        float vx0 = (x0 >= 0 && x0 < Wd) ? 1.f : 0.f;
        float vx1 = (x1 >= 0 && x1 < Wd) ? 1.f : 0.f;
        float4 wv;
        wv.x = (1.f - ly) * (1.f - lx) * vy0 * vx0;
        wv.y = (1.f - ly) * lx         * vy0 * vx1;
        wv.z = ly         * (1.f - lx) * vy1 * vx0;
        wv.w = ly         * lx         * vy1 * vx1;
        int cy0 = min(max(y0, 0), Hd - 1) << 6;
        int cy1 = min(max(y1, 0), Hd - 1) << 6;
        int cx0 = min(max(x0, 0), Wd - 1);
        int cx1 = min(max(x1, 0), Wd - 1);
        uint2 pk;
        pk.x = (unsigned)(cy0 + cx0) | ((unsigned)(cy0 + cx1) << 16);
        pk.y = (unsigned)(cy1 + cx0) | ((unsigned)(cy1 + cx1) << 16);
        Pw[idx] = wv;
        Pi[idx] = pk;
    }
    __syncthreads();

    float acc[4][4][4];
#pragma unroll
    for (int i = 0; i < 4; ++i)
#pragma unroll
        for (int j = 0; j < 4; ++j)
#pragma unroll
            for (int q = 0; q < 4; ++q) acc[i][j][q] = 0.f;

    const float* xb = g_xt + ((size_t)b << 20);
    int am = tid >> 2, ag = tid & 3;           // A-load mapping (rows am, am+64)

    // ---- prologue: build chunk 0 into stage 0 ----
    {
        int tap = 0, c1b = 0;
        const __nv_bfloat16* whp = g_wh + (size_t)c2_0 * KTOT;
        const __nv_bfloat16* wlp = g_wl + (size_t)c2_0 * KTOT;
        *(uint4*)(smem + ST_AH + am * ASTR + ag * 16) =
            *(const uint4*)(whp + (size_t)am * KTOT + ag * 8);
        *(uint4*)(smem + ST_AH + (am + 64) * ASTR + ag * 16) =
            *(const uint4*)(whp + (size_t)(am + 64) * KTOT + ag * 8);
        *(uint4*)(smem + ST_AL + am * ASTR + ag * 16) =
            *(const uint4*)(wlp + (size_t)am * KTOT + ag * 8);
        *(uint4*)(smem + ST_AL + (am + 64) * ASTR + ag * 16) =
            *(const uint4*)(wlp + (size_t)(am + 64) * KTOT + ag * 8);
#pragma unroll
        for (int i = 0; i < 16; ++i) {
            int n = wid * 16 + i;
            float4 wv = Pw[tap * 128 + n];
            uint2  pk = Pi[tap * 128 + n];
            const float* p = xb + c1b + lane;
            float v = wv.x * p[(size_t)(pk.x & 0xFFFFu) << 8]
                    + wv.y * p[(size_t)(pk.x >> 16) << 8]
                    + wv.z * p[(size_t)(pk.y & 0xFFFFu) << 8]
                    + wv.w * p[(size_t)(pk.y >> 16) << 8];
            __nv_bfloat16 hb = __float2bfloat16_rn(v);
            *(__nv_bfloat16*)(smem + ST_BH + n * ASTR + lane * 2) = hb;
            *(__nv_bfloat16*)(smem + ST_BL + n * ASTR + lane * 2) =
                __float2bfloat16_rn(v - __bfloat162float(hb));
        }
    }
    __syncthreads();

    int lr = lane & 15, ls = lane >> 4;
    int br = lane & 7,  bs = (lane >> 3) & 1;

    for (int c = 0; c < 72; ++c) {
        uint32_t scur = sb + ((c & 1) ? STAGE : 0);
        char* tnxt = smem + (((c + 1) & 1) ? STAGE : 0);
        bool hasNext = (c + 1) < 72;
        int cn = c + 1;
        int tapn = cn >> 3, c1bn = (cn & 7) << 5;
        float v[16];

        if (hasNext) {
            // A for chunk c+1: load + store immediately (stage free since last sync)
            const __nv_bfloat16* whp = g_wh + (size_t)c2_0 * KTOT + tapn * 256 + c1bn;
            const __nv_bfloat16* wlp = g_wl + (size_t)c2_0 * KTOT + tapn * 256 + c1bn;
            uint4 a0 = *(const uint4*)(whp + (size_t)am * KTOT + ag * 8);
            uint4 a1 = *(const uint4*)(whp + (size_t)(am + 64) * KTOT + ag * 8);
            uint4 a2 = *(const uint4*)(wlp + (size_t)am * KTOT + ag * 8);
            uint4 a3 = *(const uint4*)(wlp + (size_t)(am + 64) * KTOT + ag * 8);
            // B gather for chunk c+1 (values only; STS after mma)
            const float* p = xb + c1bn + lane;
#pragma unroll
            for (int i = 0; i < 16; ++i) {
                int n = wid * 16 + i;
                float4 wv = Pw[tapn * 128 + n];
                uint2  pk = Pi[tapn * 128 + n];
                v[i] = wv.x * p[(size_t)(pk.x & 0xFFFFu) << 8]
                     + wv.y * p[(size_t)(pk.x >> 16) << 8]
                     + wv.z * p[(size_t)(pk.y & 0xFFFFu) << 8]
                     + wv.w * p[(size_t)(pk.y >> 16) << 8];
            }
            *(uint4*)(tnxt + ST_AH + am * ASTR + ag * 16) = a0;
            *(uint4*)(tnxt + ST_AH + (am + 64) * ASTR + ag * 16) = a1;
            *(uint4*)(tnxt + ST_AL + am * ASTR + ag * 16) = a2;
            *(uint4*)(tnxt + ST_AL + (am + 64) * ASTR + ag * 16) = a3;
        }

        // ---- mma on stage scur ----
#pragma unroll
        for (int ks = 0; ks < 2; ++ks) {
            uint32_t bh[4][2], bl[4][2];
#pragma unroll
            for (int fn = 0; fn < 4; ++fn) {
                uint32_t ba = scur + ST_BH + (nw * 32 + fn * 8 + br) * ASTR
                            + ks * 32 + bs * 16;
                ldm_x2(bh[fn], ba);
                ldm_x2(bl[fn], ba + 10240);
            }
#pragma unroll
            for (int fm = 0; fm < 4; ++fm) {
                uint32_t ah[4], al[4];
                uint32_t aa = scur + ST_AH + (mw * 64 + fm * 16 + lr) * ASTR
                            + ks * 32 + ls * 16;
                ldm_x4(ah, aa);
                ldm_x4(al, aa + 10240);
#pragma unroll
                for (int fn = 0; fn < 4; ++fn) {
                    mma_bf16(acc[fm][fn], ah, bh[fn]);
                    mma_bf16(acc[fm][fn], ah, bl[fn]);
                    mma_bf16(acc[fm][fn], al, bh[fn]);
                }
            }
        }

        if (hasNext) {
#pragma unroll
            for (int i = 0; i < 16; ++i) {
                int n = wid * 16 + i;
                __nv_bfloat16 hb = __float2bfloat16_rn(v[i]);
                *(__nv_bfloat16*)(tnxt + ST_BH + n * ASTR + lane * 2) = hb;
                *(__nv_bfloat16*)(tnxt + ST_BL + n * ASTR + lane * 2) =
                    __float2bfloat16_rn(v[i] - __bfloat162float(hb));
            }
        }
        __syncthreads();
    }

    // ---- epilogue ----
#pragma unroll
    for (int fm = 0; fm < 4; ++fm) {
#pragma unroll
        for (int fn = 0; fn < 4; ++fn) {
            int r0   = c2_0 + mw * 64 + fm * 16 + (lane >> 2);
            int ncol = pix0 + nw * 32 + fn * 8 + ((lane & 3) << 1);
            float* p0 = out + ((size_t)(b * C2 + r0) << 12) + ncol;
            *(float2*)p0 = make_float2(acc[fm][fn][0], acc[fm][fn][1]);
            *(float2*)(p0 + (8u << 12)) = make_float2(acc[fm][fn][2], acc[fm][fn][3]);
        }
    }
}

// ---------------------------------------------------------------------------
extern "C" void kernel_launch(void* const* d_in, const int* in_sizes, int n_in,
                              void* d_out, int out_size) {
    (void)in_sizes; (void)n_in; (void)out_size;
    const float* x    = (const float*)d_in[0];
    const float* offw = (const float*)d_in[1];
    const float* offb = (const float*)d_in[2];
    const float* modw = (const float*)d_in[3];
    const float* modb = (const float*)d_in[4];
    const float* regw = (const float*)d_in[5];
    float* out = (float*)d_out;

    cudaFuncSetAttribute(dconv_mma, cudaFuncAttributeMaxDynamicSharedMemorySize,
                         SMEM_DYN);
    xt_kernel<<<dim3(32, 8, 8), 256>>>(x);
    wt_split_kernel<<<576, 1024>>>(regw);
    w27_split_kernel<<<288, 256>>>(offw, modw);
    offmod_mma<<<256, 256>>>(offb, modb);
    dconv_mma<<<dim3(256, 2), 256, SMEM_DYN>>>(out);
}